// round 2
// baseline (speedup 1.0000x reference)
#include <cuda_runtime.h>
#include <cuda_bf16.h>
#include <mma.h>
#include <math.h>

using namespace nvcuda;

#define B_ROWS 8192
#define DIM    4096
#define NPH    128      // 64 key + 64 query phase columns
#define LN_EPS 1e-5f
#define PI_F   3.14159265358979323846f

// ---------------- scratch (device globals: allocation-guard safe) -----------
__device__ float g_wkq[NPH * DIM];                    // packed [Wk;Wq]  (2 MB)
__device__ float g_phase[B_ROWS * NPH];               // raw x@Wkq^T    (4 MB)
__device__ float g_coef[B_ROWS];                      // per-row scale
__device__ float g_V[(size_t)B_ROWS * DIM];           // raw x@Wv^T   (128 MB)
__device__ float g_norm[(size_t)B_ROWS * DIM];        // normed       (128 MB)

// ---------------- pack Wk,Wq into one B matrix -------------------------------
__global__ void pack_wkq(const float* __restrict__ Wk, const float* __restrict__ Wq) {
    int i = blockIdx.x * blockDim.x + threadIdx.x;
    const int n = 64 * DIM;
    if (i < n) {
        g_wkq[i]     = Wk[i];
        g_wkq[n + i] = Wq[i];
    }
}

// ---------------- per-row phase alignment -> coef ----------------------------
__global__ void coef_kernel(const float* __restrict__ bk, const float* __restrict__ bq) {
    int row  = blockIdx.x * 8 + (threadIdx.x >> 5);
    int lane = threadIdx.x & 31;
    const float* ph = &g_phase[row * NPH];
    float s = 0.f;
#pragma unroll
    for (int p = lane; p < 64; p += 32) {
        float kp = tanhf(ph[p]      + bk[p]) * PI_F;
        float qp = tanhf(ph[64 + p] + bq[p]) * PI_F;
        s += cosf(kp - qp);
    }
#pragma unroll
    for (int o = 16; o; o >>= 1) s += __shfl_xor_sync(0xffffffffu, s, o);
    if (lane == 0) {
        float resonance = s * (1.0f / 64.0f);
        float gain = log1pf(expf(resonance + 0.5f));   // softplus
        g_coef[row] = s * gain * (1.0f / 64.0f);
    }
}

// ---------------- fused bias + row-scale + LayerNorm -------------------------
__global__ __launch_bounds__(256) void ln_kernel(const float* __restrict__ bv,
                                                 const float* __restrict__ ln_g,
                                                 const float* __restrict__ ln_b) {
    int row = blockIdx.x;
    const float* vr = &g_V[(size_t)row * DIM];
    float* nr = &g_norm[(size_t)row * DIM];
    float coef = g_coef[row];
    int tid = threadIdx.x;

    float vals[16];
    float sum = 0.f, sq = 0.f;
#pragma unroll
    for (int i = 0; i < 16; i++) {
        int k = tid + i * 256;
        float v = (vr[k] + bv[k]) * coef;
        vals[i] = v;
        sum += v; sq += v * v;
    }
    __shared__ float s1[8], s2[8];
#pragma unroll
    for (int o = 16; o; o >>= 1) {
        sum += __shfl_xor_sync(0xffffffffu, sum, o);
        sq  += __shfl_xor_sync(0xffffffffu, sq,  o);
    }
    int warp = tid >> 5, lane = tid & 31;
    if (lane == 0) { s1[warp] = sum; s2[warp] = sq; }
    __syncthreads();
    sum = 0.f; sq = 0.f;
#pragma unroll
    for (int w = 0; w < 8; w++) { sum += s1[w]; sq += s2[w]; }

    float mu   = sum * (1.0f / DIM);
    float var  = sq * (1.0f / DIM) - mu * mu;
    float rstd = rsqrtf(var + LN_EPS);
#pragma unroll
    for (int i = 0; i < 16; i++) {
        int k = tid + i * 256;
        nr[k] = (vals[i] - mu) * rstd * ln_g[k] + ln_b[k];
    }
}

// ---------------- bf16x3 split GEMM:  C[M,N] = A[M,K] @ Bw[N,K]^T ------------
// fp32 operands split into bf16 hi/lo during the smem copy.
// C = Ah*Bh + Ah*Bl + Al*Bh  (Al*Bl dropped, ~2^-16 relative)
// MODE 0: C = acc
// MODE 1: C = acc + bias[n] + addend[m*N+n]
constexpr int BM = 128, BN = 128, BK = 32;
constexpr int LDB = BK + 8;                 // bf16 leading dim (80 bytes/row)
constexpr int TILE_HALFS = BM * LDB;        // one bf16 tile

template <int MODE>
__global__ __launch_bounds__(256) void gemm_bf16x3(
    const float* __restrict__ A, const float* __restrict__ Bw,
    float* __restrict__ C, int M, int N, int K,
    const float* __restrict__ bias, const float* __restrict__ addend)
{
    __shared__ __align__(16) unsigned char smem_raw[4 * TILE_HALFS * 2];
    __nv_bfloat16* sAh = reinterpret_cast<__nv_bfloat16*>(smem_raw);
    __nv_bfloat16* sAl = sAh + TILE_HALFS;
    __nv_bfloat16* sBh = sAl + TILE_HALFS;
    __nv_bfloat16* sBl = sBh + TILE_HALFS;

    int tid  = threadIdx.x;
    int warp = tid >> 5;
    int lane = tid & 31;

    // grouped grid swizzle: consecutive blocks walk M within a GROUP-wide band
    const int num_m = M / BM, num_n = N / BN;
    const int GROUP = 8;
    int id = blockIdx.x;
    int group_size = GROUP * num_n;
    int gid = id / group_size;
    int first_m = gid * GROUP;
    int gm_sz = (num_m - first_m) < GROUP ? (num_m - first_m) : GROUP;
    int pid_m = first_m + (id % group_size) % gm_sz;
    int pid_n = (id % group_size) / gm_sz;
    int m0 = pid_m * BM;
    int n0 = pid_n * BN;

    int wm = (warp & 3) * 32;   // warp row offset in tile
    int wn = (warp >> 2) * 64;  // warp col offset in tile

    wmma::fragment<wmma::accumulator, 16, 16, 16, float> acc[2][4];
#pragma unroll
    for (int i = 0; i < 2; i++)
#pragma unroll
        for (int j = 0; j < 4; j++) wmma::fill_fragment(acc[i][j], 0.0f);

    float4 rA[4], rB[4];

    auto load_g = [&](int kk) {
#pragma unroll
        for (int p = 0; p < 4; p++) {
            int e = (p * 256 + tid) * 4;
            int r = e >> 5;
            int c = e & 31;
            rA[p] = *reinterpret_cast<const float4*>(&A [(size_t)(m0 + r) * K + kk + c]);
            rB[p] = *reinterpret_cast<const float4*>(&Bw[(size_t)(n0 + r) * K + kk + c]);
        }
    };
    auto store_s = [&]() {
#pragma unroll
        for (int p = 0; p < 4; p++) {
            int e = (p * 256 + tid) * 4;
            int r = e >> 5;
            int c = e & 31;
            float va[4] = {rA[p].x, rA[p].y, rA[p].z, rA[p].w};
            float vb[4] = {rB[p].x, rB[p].y, rB[p].z, rB[p].w};
#pragma unroll
            for (int q = 0; q < 4; q++) {
                __nv_bfloat16 h = __float2bfloat16_rn(va[q]);
                sAh[r * LDB + c + q] = h;
                sAl[r * LDB + c + q] = __float2bfloat16_rn(va[q] - __bfloat162float(h));
                __nv_bfloat16 g = __float2bfloat16_rn(vb[q]);
                sBh[r * LDB + c + q] = g;
                sBl[r * LDB + c + q] = __float2bfloat16_rn(vb[q] - __bfloat162float(g));
            }
        }
    };

    load_g(0);
    store_s();
    __syncthreads();

    for (int k0 = 0; k0 < K; k0 += BK) {
        bool has_next = (k0 + BK) < K;
        if (has_next) load_g(k0 + BK);   // overlap gmem with MMA below

#pragma unroll
        for (int ks = 0; ks < BK; ks += 16) {
            wmma::fragment<wmma::matrix_a, 16, 16, 16, __nv_bfloat16, wmma::row_major> ah[2], al[2];
            wmma::fragment<wmma::matrix_b, 16, 16, 16, __nv_bfloat16, wmma::col_major> bh[4], bl[4];
#pragma unroll
            for (int i = 0; i < 2; i++) {
                wmma::load_matrix_sync(ah[i], &sAh[(wm + i * 16) * LDB + ks], LDB);
                wmma::load_matrix_sync(al[i], &sAl[(wm + i * 16) * LDB + ks], LDB);
            }
#pragma unroll
            for (int j = 0; j < 4; j++) {
                wmma::load_matrix_sync(bh[j], &sBh[(wn + j * 16) * LDB + ks], LDB);
                wmma::load_matrix_sync(bl[j], &sBl[(wn + j * 16) * LDB + ks], LDB);
            }
#pragma unroll
            for (int i = 0; i < 2; i++)
#pragma unroll
                for (int j = 0; j < 4; j++) {
                    wmma::mma_sync(acc[i][j], ah[i], bh[j], acc[i][j]);
                    wmma::mma_sync(acc[i][j], ah[i], bl[j], acc[i][j]);
                    wmma::mma_sync(acc[i][j], al[i], bh[j], acc[i][j]);
                }
        }
        __syncthreads();
        if (has_next) {
            store_s();
            __syncthreads();
        }
    }

    // epilogue: per-warp smem staging (aliases the operand tiles — all MMA done)
    float* stage = reinterpret_cast<float*>(smem_raw) + warp * 320;
#pragma unroll
    for (int i = 0; i < 2; i++) {
#pragma unroll
        for (int j = 0; j < 4; j++) {
            wmma::store_matrix_sync(stage, acc[i][j], 20, wmma::mem_row_major);
            __syncwarp();
            int gm = m0 + wm + i * 16;
            int gn = n0 + wn + j * 16;
#pragma unroll
            for (int e = 0; e < 8; e++) {
                int idx = e * 32 + lane;
                int rr = idx >> 4;
                int cc = idx & 15;
                float v = stage[rr * 20 + cc];
                size_t go = (size_t)(gm + rr) * N + gn + cc;
                if (MODE == 1) v += bias[gn + cc] + addend[go];
                C[go] = v;
            }
            __syncwarp();
        }
    }
}

// ---------------- launch -----------------------------------------------------
extern "C" void kernel_launch(void* const* d_in, const int* in_sizes, int n_in,
                              void* d_out, int out_size) {
    const float* x    = (const float*)d_in[0];
    const float* Wk   = (const float*)d_in[1];
    const float* bk   = (const float*)d_in[2];
    const float* Wq   = (const float*)d_in[3];
    const float* bq   = (const float*)d_in[4];
    const float* Wv   = (const float*)d_in[5];
    const float* bv   = (const float*)d_in[6];
    const float* ln_g = (const float*)d_in[7];
    const float* ln_b = (const float*)d_in[8];
    const float* Wo   = (const float*)d_in[9];
    const float* bo   = (const float*)d_in[10];
    float* out = (float*)d_out;

    float *p_wkq, *p_phase, *p_V, *p_norm;
    cudaGetSymbolAddress((void**)&p_wkq,   g_wkq);
    cudaGetSymbolAddress((void**)&p_phase, g_phase);
    cudaGetSymbolAddress((void**)&p_V,     g_V);
    cudaGetSymbolAddress((void**)&p_norm,  g_norm);

    // 1. pack [Wk;Wq]
    pack_wkq<<<(64 * DIM + 255) / 256, 256>>>(Wk, Wq);

    // 2. phase scores: [B,128] = x @ Wkq^T
    gemm_bf16x3<0><<<(B_ROWS / BM) * (NPH / BN), 256>>>(
        x, p_wkq, p_phase, B_ROWS, NPH, DIM, nullptr, nullptr);

    // 3. per-row coef
    coef_kernel<<<B_ROWS / 8, 256>>>(bk, bq);

    // 4. V raw: [B,DIM] = x @ Wv^T
    gemm_bf16x3<0><<<(B_ROWS / BM) * (DIM / BN), 256>>>(
        x, Wv, p_V, B_ROWS, DIM, DIM, nullptr, nullptr);

    // 5. bias + coef scale + LayerNorm -> normed
    ln_kernel<<<B_ROWS, 256>>>(bv, ln_g, ln_b);

    // 6. out = x + normed @ Wo^T + bo
    gemm_bf16x3<1><<<(B_ROWS / BM) * (DIM / BN), 256>>>(
        p_norm, Wo, out, B_ROWS, DIM, DIM, bo, x);
}

// round 3
// speedup vs baseline: 1.4435x; 1.4435x over previous
#include <cuda_runtime.h>
#include <cuda_bf16.h>
#include <mma.h>
#include <math.h>

using namespace nvcuda;

#define B_ROWS 8192
#define DIM    4096
#define NPH    128
#define K3     (3 * DIM)          // 12288: [hi | cross | cross] split-K
#define LN_EPS 1e-5f
#define PI_F   3.14159265358979323846f

// ---------------- scratch (device globals) ----------------------------------
__device__ __nv_bfloat16 g_x3 [(size_t)B_ROWS * K3];   // x  split  [h|h|l] 192MB
__device__ __nv_bfloat16 g_n3 [(size_t)B_ROWS * K3];   // normed    [h|h|l] 192MB
__device__ __nv_bfloat16 g_wv3[(size_t)DIM * K3];      // Wv split  [h|l|h]  96MB
__device__ __nv_bfloat16 g_wo3[(size_t)DIM * K3];      // Wo split  [h|l|h]  96MB
__device__ __nv_bfloat16 g_wkq3[(size_t)NPH * K3];     // [Wk;Wq]   [h|l|h]   3MB
__device__ float g_phase[B_ROWS * NPH];
__device__ float g_coef[B_ROWS];
__device__ float g_V[(size_t)B_ROWS * DIM];

// ---------------- cp.async helpers ------------------------------------------
__device__ __forceinline__ void cp_async16(void* smem, const void* gmem) {
    unsigned s = (unsigned)__cvta_generic_to_shared(smem);
    asm volatile("cp.async.cg.shared.global [%0], [%1], 16;\n" :: "r"(s), "l"(gmem));
}
__device__ __forceinline__ void cp_commit() { asm volatile("cp.async.commit_group;\n"); }
template <int N> __device__ __forceinline__ void cp_wait() {
    asm volatile("cp.async.wait_group %0;\n" :: "n"(N));
}

// ---------------- fp32 -> bf16 hi/lo split, 3-segment layout ----------------
// ASIDE=true  : out = [h | h | l]   (activation side)
// ASIDE=false : out = [h | l | h]   (weight side)
template <bool ASIDE>
__global__ void split3(const float* __restrict__ in, __nv_bfloat16* __restrict__ out,
                       size_t n_vec4) {   // n_vec4 = R*K/4, K == DIM
    size_t i = (size_t)blockIdx.x * blockDim.x + threadIdx.x;
    if (i >= n_vec4) return;
    size_t e = i * 4;
    size_t r = e / DIM;
    int    k = (int)(e % DIM);
    float4 v = *reinterpret_cast<const float4*>(in + e);
    float vv[4] = {v.x, v.y, v.z, v.w};
    union { __nv_bfloat16 b[4]; uint2 u; } H, L;
#pragma unroll
    for (int q = 0; q < 4; q++) {
        H.b[q] = __float2bfloat16_rn(vv[q]);
        L.b[q] = __float2bfloat16_rn(vv[q] - __bfloat162float(H.b[q]));
    }
    __nv_bfloat16* o = out + r * (size_t)K3 + k;
    *reinterpret_cast<uint2*>(o)           = H.u;
    *reinterpret_cast<uint2*>(o + DIM)     = ASIDE ? H.u : L.u;
    *reinterpret_cast<uint2*>(o + 2 * DIM) = ASIDE ? L.u : H.u;
}

// ---------------- per-row phase alignment -> coef ----------------------------
__global__ void coef_kernel(const float* __restrict__ bk, const float* __restrict__ bq) {
    int row  = blockIdx.x * 8 + (threadIdx.x >> 5);
    int lane = threadIdx.x & 31;
    const float* ph = &g_phase[row * NPH];
    float s = 0.f;
#pragma unroll
    for (int p = lane; p < 64; p += 32) {
        float kp = tanhf(ph[p]      + bk[p]) * PI_F;
        float qp = tanhf(ph[64 + p] + bq[p]) * PI_F;
        s += cosf(kp - qp);
    }
#pragma unroll
    for (int o = 16; o; o >>= 1) s += __shfl_xor_sync(0xffffffffu, s, o);
    if (lane == 0) {
        float gain = log1pf(expf(s * (1.0f / 64.0f) + 0.5f));
        g_coef[row] = s * gain * (1.0f / 64.0f);
    }
}

// ------- fused bias + row-scale + LayerNorm -> split bf16 [h|h|l] -----------
__global__ __launch_bounds__(256) void ln_kernel(const float* __restrict__ bv,
                                                 const float* __restrict__ ln_g,
                                                 const float* __restrict__ ln_b) {
    int row = blockIdx.x;
    const float* vr = g_V + (size_t)row * DIM;
    __nv_bfloat16* nr = g_n3 + (size_t)row * K3;
    float coef = g_coef[row];
    int tid = threadIdx.x;

    float vals[16];
    float sum = 0.f, sq = 0.f;
#pragma unroll
    for (int j = 0; j < 4; j++) {
        int k = (tid + j * 256) * 4;
        float4 v = *reinterpret_cast<const float4*>(vr + k);
        float4 b = *reinterpret_cast<const float4*>(bv + k);
        float t0 = (v.x + b.x) * coef, t1 = (v.y + b.y) * coef;
        float t2 = (v.z + b.z) * coef, t3 = (v.w + b.w) * coef;
        vals[j*4+0]=t0; vals[j*4+1]=t1; vals[j*4+2]=t2; vals[j*4+3]=t3;
        sum += t0+t1+t2+t3;
        sq  += t0*t0+t1*t1+t2*t2+t3*t3;
    }
    __shared__ float s1[8], s2[8];
#pragma unroll
    for (int o = 16; o; o >>= 1) {
        sum += __shfl_xor_sync(0xffffffffu, sum, o);
        sq  += __shfl_xor_sync(0xffffffffu, sq,  o);
    }
    int warp = tid >> 5, lane = tid & 31;
    if (lane == 0) { s1[warp] = sum; s2[warp] = sq; }
    __syncthreads();
    sum = 0.f; sq = 0.f;
#pragma unroll
    for (int w = 0; w < 8; w++) { sum += s1[w]; sq += s2[w]; }

    float mu   = sum * (1.0f / DIM);
    float var  = sq * (1.0f / DIM) - mu * mu;
    float rstd = rsqrtf(var + LN_EPS);
#pragma unroll
    for (int j = 0; j < 4; j++) {
        int k = (tid + j * 256) * 4;
        float4 g = *reinterpret_cast<const float4*>(ln_g + k);
        float4 bb = *reinterpret_cast<const float4*>(ln_b + k);
        float o0 = (vals[j*4+0]-mu)*rstd*g.x + bb.x;
        float o1 = (vals[j*4+1]-mu)*rstd*g.y + bb.y;
        float o2 = (vals[j*4+2]-mu)*rstd*g.z + bb.z;
        float o3 = (vals[j*4+3]-mu)*rstd*g.w + bb.w;
        float oo[4] = {o0,o1,o2,o3};
        union { __nv_bfloat16 b[4]; uint2 u; } H, L;
#pragma unroll
        for (int q = 0; q < 4; q++) {
            H.b[q] = __float2bfloat16_rn(oo[q]);
            L.b[q] = __float2bfloat16_rn(oo[q] - __bfloat162float(H.b[q]));
        }
        *reinterpret_cast<uint2*>(nr + k)           = H.u;  // hi
        *reinterpret_cast<uint2*>(nr + DIM + k)     = H.u;  // hi (cross with Bl)
        *reinterpret_cast<uint2*>(nr + 2*DIM + k)   = L.u;  // lo (cross with Bh)
    }
}

// ---------------- pipelined bf16 GEMM:  C[M,N] = A[M,K3] @ Bw[N,K3]^T --------
// MODE 0: C = acc     MODE 1: C = acc + bias[n] + addend[m*N+n]
constexpr int BM = 128, BN = 128, BKE = 64;     // bf16 k-elements per tile
constexpr int LDSB = 72;                         // padded leading dim (elements)
constexpr int STAGES = 3;
constexpr int STAGE_ELEMS = BM * LDSB;           // per operand per stage
constexpr size_t GEMM_SMEM = (size_t)STAGES * 2 * STAGE_ELEMS * sizeof(__nv_bfloat16);

template <int MODE>
__global__ __launch_bounds__(256, 2) void gemm_split(
    const __nv_bfloat16* __restrict__ A, const __nv_bfloat16* __restrict__ Bw,
    float* __restrict__ C, int M, int N,
    const float* __restrict__ bias, const float* __restrict__ addend)
{
    extern __shared__ __align__(128) unsigned char dsmem[];
    __nv_bfloat16* sA = reinterpret_cast<__nv_bfloat16*>(dsmem);
    __nv_bfloat16* sB = sA + STAGES * STAGE_ELEMS;

    int tid  = threadIdx.x;
    int warp = tid >> 5;
    int lane = tid & 31;

    // grouped grid swizzle (GROUP_M = 8)
    const int num_m = M / BM, num_n = N / BN;
    const int GROUP = 8;
    int id = blockIdx.x;
    int group_size = GROUP * num_n;
    int gid = id / group_size;
    int first_m = gid * GROUP;
    int gm_sz = (num_m - first_m) < GROUP ? (num_m - first_m) : GROUP;
    int pid_m = first_m + (id % group_size) % gm_sz;
    int pid_n = (id % group_size) / gm_sz;
    int m0 = pid_m * BM;
    int n0 = pid_n * BN;

    int wm = (warp & 3) * 32;
    int wn = (warp >> 2) * 64;

    // per-thread load geometry: 8 x 16B chunks per row of 64 bf16
    int chunk = tid & 7;          // 0..7  -> col = chunk*8
    int row0  = tid >> 3;         // 0..31 -> + pass*32

    const __nv_bfloat16* gA = A  + (size_t)m0 * K3 + chunk * 8;
    const __nv_bfloat16* gB = Bw + (size_t)n0 * K3 + chunk * 8;

    auto load_tile = [&](int kt, int stg) {
        size_t koff = (size_t)kt * BKE;
        __nv_bfloat16* dA = sA + stg * STAGE_ELEMS + chunk * 8;
        __nv_bfloat16* dB = sB + stg * STAGE_ELEMS + chunk * 8;
#pragma unroll
        for (int p = 0; p < 4; p++) {
            int r = row0 + p * 32;
            cp_async16(dA + r * LDSB, gA + (size_t)r * K3 + koff);
            cp_async16(dB + r * LDSB, gB + (size_t)r * K3 + koff);
        }
    };

    wmma::fragment<wmma::accumulator, 16, 16, 16, float> acc[2][4];
#pragma unroll
    for (int i = 0; i < 2; i++)
#pragma unroll
        for (int j = 0; j < 4; j++) wmma::fill_fragment(acc[i][j], 0.0f);

    const int nt = K3 / BKE;   // 192
#pragma unroll
    for (int s = 0; s < STAGES - 1; s++) { load_tile(s, s); cp_commit(); }

    for (int it = 0; it < nt; it++) {
        cp_wait<STAGES - 2>();
        __syncthreads();
        int pre = it + STAGES - 1;
        if (pre < nt) { load_tile(pre, pre % STAGES); cp_commit(); }

        const __nv_bfloat16* tA = sA + (it % STAGES) * STAGE_ELEMS;
        const __nv_bfloat16* tB = sB + (it % STAGES) * STAGE_ELEMS;
#pragma unroll
        for (int ks = 0; ks < BKE; ks += 16) {
            wmma::fragment<wmma::matrix_a, 16, 16, 16, __nv_bfloat16, wmma::row_major> af[2];
            wmma::fragment<wmma::matrix_b, 16, 16, 16, __nv_bfloat16, wmma::col_major> bf[4];
#pragma unroll
            for (int i = 0; i < 2; i++)
                wmma::load_matrix_sync(af[i], tA + (wm + i * 16) * LDSB + ks, LDSB);
#pragma unroll
            for (int j = 0; j < 4; j++)
                wmma::load_matrix_sync(bf[j], tB + (wn + j * 16) * LDSB + ks, LDSB);
#pragma unroll
            for (int i = 0; i < 2; i++)
#pragma unroll
                for (int j = 0; j < 4; j++)
                    wmma::mma_sync(acc[i][j], af[i], bf[j], acc[i][j]);
        }
    }

    cp_wait<0>();
    __syncthreads();

    // epilogue: per-warp smem staging (aliases operand tiles)
    float* stage = reinterpret_cast<float*>(dsmem) + warp * 320;
#pragma unroll
    for (int i = 0; i < 2; i++) {
#pragma unroll
        for (int j = 0; j < 4; j++) {
            wmma::store_matrix_sync(stage, acc[i][j], 20, wmma::mem_row_major);
            __syncwarp();
            int gm = m0 + wm + i * 16;
            int gn = n0 + wn + j * 16;
#pragma unroll
            for (int e = 0; e < 8; e++) {
                int idx = e * 32 + lane;
                int rr = idx >> 4;
                int cc = idx & 15;
                float v = stage[rr * 20 + cc];
                size_t go = (size_t)(gm + rr) * N + gn + cc;
                if (MODE == 1) v += bias[gn + cc] + addend[go];
                C[go] = v;
            }
            __syncwarp();
        }
    }
}

// ---------------- launch -----------------------------------------------------
extern "C" void kernel_launch(void* const* d_in, const int* in_sizes, int n_in,
                              void* d_out, int out_size) {
    const float* x    = (const float*)d_in[0];
    const float* Wk   = (const float*)d_in[1];
    const float* bk   = (const float*)d_in[2];
    const float* Wq   = (const float*)d_in[3];
    const float* bq   = (const float*)d_in[4];
    const float* Wv   = (const float*)d_in[5];
    const float* bv   = (const float*)d_in[6];
    const float* ln_g = (const float*)d_in[7];
    const float* ln_b = (const float*)d_in[8];
    const float* Wo   = (const float*)d_in[9];
    const float* bo   = (const float*)d_in[10];
    float* out = (float*)d_out;

    __nv_bfloat16 *p_x3, *p_n3, *p_wv3, *p_wo3, *p_wkq3;
    float *p_phase, *p_V;
    cudaGetSymbolAddress((void**)&p_x3,   g_x3);
    cudaGetSymbolAddress((void**)&p_n3,   g_n3);
    cudaGetSymbolAddress((void**)&p_wv3,  g_wv3);
    cudaGetSymbolAddress((void**)&p_wo3,  g_wo3);
    cudaGetSymbolAddress((void**)&p_wkq3, g_wkq3);
    cudaGetSymbolAddress((void**)&p_phase, g_phase);
    cudaGetSymbolAddress((void**)&p_V,     g_V);

    cudaFuncSetAttribute(gemm_split<0>, cudaFuncAttributeMaxDynamicSharedMemorySize, (int)GEMM_SMEM);
    cudaFuncSetAttribute(gemm_split<1>, cudaFuncAttributeMaxDynamicSharedMemorySize, (int)GEMM_SMEM);

    // 1. splits
    {
        size_t nx = (size_t)B_ROWS * DIM / 4;
        split3<true ><<<(unsigned)((nx + 255) / 256), 256>>>(x, p_x3, nx);
        size_t nw = (size_t)DIM * DIM / 4;
        split3<false><<<(unsigned)((nw + 255) / 256), 256>>>(Wv, p_wv3, nw);
        split3<false><<<(unsigned)((nw + 255) / 256), 256>>>(Wo, p_wo3, nw);
        size_t nk = (size_t)64 * DIM / 4;
        split3<false><<<(unsigned)((nk + 255) / 256), 256>>>(Wk, p_wkq3, nk);
        split3<false><<<(unsigned)((nk + 255) / 256), 256>>>(Wq, p_wkq3 + (size_t)64 * K3, nk);
    }

    // 2. phase scores: [B,128] = x @ Wkq^T
    gemm_split<0><<<(B_ROWS / BM) * (NPH / BN), 256, GEMM_SMEM>>>(
        p_x3, p_wkq3, p_phase, B_ROWS, NPH, nullptr, nullptr);

    // 3. per-row coef
    coef_kernel<<<B_ROWS / 8, 256>>>(bk, bq);

    // 4. V raw: [B,DIM] = x @ Wv^T
    gemm_split<0><<<(B_ROWS / BM) * (DIM / BN), 256, GEMM_SMEM>>>(
        p_x3, p_wv3, p_V, B_ROWS, DIM, nullptr, nullptr);

    // 5. bias + coef scale + LayerNorm -> split bf16 normed
    ln_kernel<<<B_ROWS, 256>>>(bv, ln_g, ln_b);

    // 6. out = x + normed @ Wo^T + bo
    gemm_split<1><<<(B_ROWS / BM) * (DIM / BN), 256, GEMM_SMEM>>>(
        p_n3, p_wo3, out, B_ROWS, DIM, bo, x);
}

// round 5
// speedup vs baseline: 4.3824x; 3.0360x over previous
#include <cuda_runtime.h>
#include <cuda_bf16.h>
#include <cuda_fp16.h>
#include <mma.h>
#include <math.h>
#include <stdint.h>

using namespace nvcuda;

#define B_ROWS 8192
#define DIM    4096
#define NPH    128
#define K3     (3 * DIM)
#define LN_EPS 1e-5f
#define PI_F   3.14159265358979323846f

// ---------------- scratch (device globals) ----------------------------------
__device__ __nv_bfloat16 g_x3 [(size_t)B_ROWS * K3];    // x split [h|h|l] (phase A)
__device__ __nv_bfloat16 g_wkq3[(size_t)NPH * K3];      // [Wk;Wq] split [h|l|h]
__device__ __half g_xh [(size_t)B_ROWS * DIM];          // x   fp16
__device__ __half g_wvh[(size_t)DIM * DIM];             // Wv  fp16
__device__ __half g_woh[(size_t)DIM * DIM];             // Wo  fp16
__device__ __half g_nh [(size_t)B_ROWS * DIM];          // normed fp16
__device__ float g_phase[3 * (size_t)B_ROWS * NPH];     // 3 split-K partials
__device__ float g_coef[B_ROWS];
__device__ float g_V[(size_t)B_ROWS * DIM];

// ---------------- cp.async helpers ------------------------------------------
__device__ __forceinline__ void cp_async16(void* smem, const void* gmem) {
    unsigned s = (unsigned)__cvta_generic_to_shared(smem);
    asm volatile("cp.async.cg.shared.global [%0], [%1], 16;\n" :: "r"(s), "l"(gmem));
}
__device__ __forceinline__ void cp_commit() { asm volatile("cp.async.commit_group;\n"); }
template <int N> __device__ __forceinline__ void cp_wait() {
    asm volatile("cp.async.wait_group %0;\n" :: "n"(N));
}

// ---------------- fp32 -> bf16 hi/lo split, 3-segment layout ----------------
template <bool ASIDE>
__global__ void split3(const float* __restrict__ in, __nv_bfloat16* __restrict__ out,
                       size_t n_vec4) {
    size_t i = (size_t)blockIdx.x * blockDim.x + threadIdx.x;
    if (i >= n_vec4) return;
    size_t e = i * 4;
    size_t r = e / DIM;
    int    k = (int)(e % DIM);
    float4 v = *reinterpret_cast<const float4*>(in + e);
    float vv[4] = {v.x, v.y, v.z, v.w};
    union { __nv_bfloat16 b[4]; uint2 u; } H, L;
#pragma unroll
    for (int q = 0; q < 4; q++) {
        H.b[q] = __float2bfloat16_rn(vv[q]);
        L.b[q] = __float2bfloat16_rn(vv[q] - __bfloat162float(H.b[q]));
    }
    __nv_bfloat16* o = out + r * (size_t)K3 + k;
    *reinterpret_cast<uint2*>(o)           = H.u;
    *reinterpret_cast<uint2*>(o + DIM)     = ASIDE ? H.u : L.u;
    *reinterpret_cast<uint2*>(o + 2 * DIM) = ASIDE ? L.u : H.u;
}

// ---------------- fp32 -> fp16 convert ---------------------------------------
__global__ void to_half(const float* __restrict__ in, __half* __restrict__ out, size_t n_vec4) {
    size_t i = (size_t)blockIdx.x * blockDim.x + threadIdx.x;
    if (i >= n_vec4) return;
    float4 v = *reinterpret_cast<const float4*>(in + i * 4);
    __half2 h0 = __floats2half2_rn(v.x, v.y);
    __half2 h1 = __floats2half2_rn(v.z, v.w);
    uint2 u = {*reinterpret_cast<uint32_t*>(&h0), *reinterpret_cast<uint32_t*>(&h1)};
    *reinterpret_cast<uint2*>(out + i * 4) = u;
}

// ---------------- per-row phase alignment -> coef (sums 3 partials) ----------
__global__ void coef_kernel(const float* __restrict__ bk, const float* __restrict__ bq) {
    int row  = blockIdx.x * 8 + (threadIdx.x >> 5);
    int lane = threadIdx.x & 31;
    const size_t SEG = (size_t)B_ROWS * NPH;
    const float* ph = &g_phase[(size_t)row * NPH];
    float s = 0.f;
#pragma unroll
    for (int p = lane; p < 64; p += 32) {
        float rk = ph[p]      + ph[SEG + p]      + ph[2*SEG + p];
        float rq = ph[64 + p] + ph[SEG + 64 + p] + ph[2*SEG + 64 + p];
        float kp = tanhf(rk + bk[p]) * PI_F;
        float qp = tanhf(rq + bq[p]) * PI_F;
        s += cosf(kp - qp);
    }
#pragma unroll
    for (int o = 16; o; o >>= 1) s += __shfl_xor_sync(0xffffffffu, s, o);
    if (lane == 0) {
        float gain = log1pf(expf(s * (1.0f / 64.0f) + 0.5f));
        g_coef[row] = s * gain * (1.0f / 64.0f);
    }
}

// ------- fused bias + row-scale + LayerNorm -> fp16 normed -------------------
__global__ __launch_bounds__(256) void ln_kernel(const float* __restrict__ bv,
                                                 const float* __restrict__ ln_g,
                                                 const float* __restrict__ ln_b) {
    int row = blockIdx.x;
    const float* vr = g_V + (size_t)row * DIM;
    __half* nr = g_nh + (size_t)row * DIM;
    float coef = g_coef[row];
    int tid = threadIdx.x;

    float vals[16];
    float sum = 0.f, sq = 0.f;
#pragma unroll
    for (int j = 0; j < 4; j++) {
        int k = (tid + j * 256) * 4;
        float4 v = *reinterpret_cast<const float4*>(vr + k);
        float4 b = *reinterpret_cast<const float4*>(bv + k);
        float t0 = (v.x + b.x) * coef, t1 = (v.y + b.y) * coef;
        float t2 = (v.z + b.z) * coef, t3 = (v.w + b.w) * coef;
        vals[j*4+0]=t0; vals[j*4+1]=t1; vals[j*4+2]=t2; vals[j*4+3]=t3;
        sum += t0+t1+t2+t3;
        sq  += t0*t0+t1*t1+t2*t2+t3*t3;
    }
    __shared__ float s1[8], s2[8];
#pragma unroll
    for (int o = 16; o; o >>= 1) {
        sum += __shfl_xor_sync(0xffffffffu, sum, o);
        sq  += __shfl_xor_sync(0xffffffffu, sq,  o);
    }
    int warp = tid >> 5, lane = tid & 31;
    if (lane == 0) { s1[warp] = sum; s2[warp] = sq; }
    __syncthreads();
    sum = 0.f; sq = 0.f;
#pragma unroll
    for (int w = 0; w < 8; w++) { sum += s1[w]; sq += s2[w]; }

    float mu   = sum * (1.0f / DIM);
    float var  = sq * (1.0f / DIM) - mu * mu;
    float rstd = rsqrtf(var + LN_EPS);
#pragma unroll
    for (int j = 0; j < 4; j++) {
        int k = (tid + j * 256) * 4;
        float4 g = *reinterpret_cast<const float4*>(ln_g + k);
        float4 bb = *reinterpret_cast<const float4*>(ln_b + k);
        __half2 h0 = __floats2half2_rn((vals[j*4+0]-mu)*rstd*g.x + bb.x,
                                       (vals[j*4+1]-mu)*rstd*g.y + bb.y);
        __half2 h1 = __floats2half2_rn((vals[j*4+2]-mu)*rstd*g.z + bb.z,
                                       (vals[j*4+3]-mu)*rstd*g.w + bb.w);
        uint2 u = {*reinterpret_cast<uint32_t*>(&h0), *reinterpret_cast<uint32_t*>(&h1)};
        *reinterpret_cast<uint2*>(nr + k) = u;
    }
}

// ---------------- pipelined 16-bit GEMM:  C = A[M,K] @ Bw[N,K]^T -------------
// T in {__half, __nv_bfloat16}. Split-K via blockIdx.y (partials at C+seg*M*N).
// MODE 0: C = acc     MODE 1: C = acc + bias[n] + addend[m*N+n]
constexpr int BM = 128, BN = 128, BKE = 64;
constexpr int LDSB = 72;
constexpr int STAGES = 3;
constexpr int STAGE_ELEMS = BM * LDSB;
constexpr size_t GEMM_SMEM = (size_t)STAGES * 2 * STAGE_ELEMS * 2;

template <typename T, int MODE>
__global__ __launch_bounds__(256, 2) void gemm16(
    const T* __restrict__ A, int lda, const T* __restrict__ Bw, int ldb, int K,
    float* __restrict__ C, int M, int N,
    const float* __restrict__ bias, const float* __restrict__ addend)
{
    extern __shared__ __align__(128) unsigned char dsmem[];
    T* sA = reinterpret_cast<T*>(dsmem);
    T* sB = sA + STAGES * STAGE_ELEMS;

    // split-K segment
    A  += (size_t)blockIdx.y * K;      // segment columns within lda-row
    Bw += (size_t)blockIdx.y * K;
    C  += (size_t)blockIdx.y * (size_t)M * N;

    int tid  = threadIdx.x;
    int warp = tid >> 5;
    int lane = tid & 31;

    const int num_m = M / BM, num_n = N / BN;
    const int GROUP = 8;
    int id = blockIdx.x;
    int group_size = GROUP * num_n;
    int gid = id / group_size;
    int first_m = gid * GROUP;
    int gm_sz = (num_m - first_m) < GROUP ? (num_m - first_m) : GROUP;
    int pid_m = first_m + (id % group_size) % gm_sz;
    int pid_n = (id % group_size) / gm_sz;
    int m0 = pid_m * BM;
    int n0 = pid_n * BN;

    int wm = (warp & 3) * 32;
    int wn = (warp >> 2) * 64;

    int chunk = tid & 7;
    int row0  = tid >> 3;

    const T* gA = A  + (size_t)m0 * lda + chunk * 8;
    const T* gB = Bw + (size_t)n0 * ldb + chunk * 8;

    auto load_tile = [&](int kt, int stg) {
        size_t koff = (size_t)kt * BKE;
        T* dA = sA + stg * STAGE_ELEMS + chunk * 8;
        T* dB = sB + stg * STAGE_ELEMS + chunk * 8;
#pragma unroll
        for (int p = 0; p < 4; p++) {
            int r = row0 + p * 32;
            cp_async16(dA + r * LDSB, gA + (size_t)r * lda + koff);
            cp_async16(dB + r * LDSB, gB + (size_t)r * ldb + koff);
        }
    };

    wmma::fragment<wmma::accumulator, 16, 16, 16, float> acc[2][4];
#pragma unroll
    for (int i = 0; i < 2; i++)
#pragma unroll
        for (int j = 0; j < 4; j++) wmma::fill_fragment(acc[i][j], 0.0f);

    const int nt = K / BKE;
#pragma unroll
    for (int s = 0; s < STAGES - 1; s++) { load_tile(s, s); cp_commit(); }

    for (int it = 0; it < nt; it++) {
        cp_wait<STAGES - 2>();
        __syncthreads();
        int pre = it + STAGES - 1;
        if (pre < nt) { load_tile(pre, pre % STAGES); cp_commit(); }

        const T* tA = sA + (it % STAGES) * STAGE_ELEMS;
        const T* tB = sB + (it % STAGES) * STAGE_ELEMS;
#pragma unroll
        for (int ks = 0; ks < BKE; ks += 16) {
            wmma::fragment<wmma::matrix_a, 16, 16, 16, T, wmma::row_major> af[2];
            wmma::fragment<wmma::matrix_b, 16, 16, 16, T, wmma::col_major> bf[4];
#pragma unroll
            for (int i = 0; i < 2; i++)
                wmma::load_matrix_sync(af[i], tA + (wm + i * 16) * LDSB + ks, LDSB);
#pragma unroll
            for (int j = 0; j < 4; j++)
                wmma::load_matrix_sync(bf[j], tB + (wn + j * 16) * LDSB + ks, LDSB);
#pragma unroll
            for (int i = 0; i < 2; i++)
#pragma unroll
                for (int j = 0; j < 4; j++)
                    wmma::mma_sync(acc[i][j], af[i], bf[j], acc[i][j]);
        }
    }

    cp_wait<0>();
    __syncthreads();

    float* stage = reinterpret_cast<float*>(dsmem) + warp * 320;
#pragma unroll
    for (int i = 0; i < 2; i++) {
#pragma unroll
        for (int j = 0; j < 4; j++) {
            wmma::store_matrix_sync(stage, acc[i][j], 20, wmma::mem_row_major);
            __syncwarp();
            int gm = m0 + wm + i * 16;
            int gn = n0 + wn + j * 16;
#pragma unroll
            for (int e = 0; e < 8; e++) {
                int idx = e * 32 + lane;
                int rr = idx >> 4;
                int cc = idx & 15;
                float v = stage[rr * 20 + cc];
                size_t go = (size_t)(gm + rr) * N + gn + cc;
                if (MODE == 1) v += bias[gn + cc] + addend[go];
                C[go] = v;
            }
            __syncwarp();
        }
    }
}

// ---------------- launch -----------------------------------------------------
extern "C" void kernel_launch(void* const* d_in, const int* in_sizes, int n_in,
                              void* d_out, int out_size) {
    const float* x    = (const float*)d_in[0];
    const float* Wk   = (const float*)d_in[1];
    const float* bk   = (const float*)d_in[2];
    const float* Wq   = (const float*)d_in[3];
    const float* bq   = (const float*)d_in[4];
    const float* Wv   = (const float*)d_in[5];
    const float* bv   = (const float*)d_in[6];
    const float* ln_g = (const float*)d_in[7];
    const float* ln_b = (const float*)d_in[8];
    const float* Wo   = (const float*)d_in[9];
    const float* bo   = (const float*)d_in[10];
    float* out = (float*)d_out;

    __nv_bfloat16 *p_x3, *p_wkq3;
    __half *p_xh, *p_wvh, *p_woh, *p_nh;
    float *p_phase, *p_V;
    cudaGetSymbolAddress((void**)&p_x3,   g_x3);
    cudaGetSymbolAddress((void**)&p_wkq3, g_wkq3);
    cudaGetSymbolAddress((void**)&p_xh,   g_xh);
    cudaGetSymbolAddress((void**)&p_wvh,  g_wvh);
    cudaGetSymbolAddress((void**)&p_woh,  g_woh);
    cudaGetSymbolAddress((void**)&p_nh,   g_nh);
    cudaGetSymbolAddress((void**)&p_phase, g_phase);
    cudaGetSymbolAddress((void**)&p_V,     g_V);

    cudaFuncSetAttribute((const void*)gemm16<__half,0>,
                         cudaFuncAttributeMaxDynamicSharedMemorySize, (int)GEMM_SMEM);
    cudaFuncSetAttribute((const void*)gemm16<__half,1>,
                         cudaFuncAttributeMaxDynamicSharedMemorySize, (int)GEMM_SMEM);
    cudaFuncSetAttribute((const void*)gemm16<__nv_bfloat16,0>,
                         cudaFuncAttributeMaxDynamicSharedMemorySize, (int)GEMM_SMEM);

    // 1. precision prep
    size_t nx = (size_t)B_ROWS * DIM / 4;
    split3<true ><<<(unsigned)((nx + 255) / 256), 256>>>(x, p_x3, nx);
    to_half<<<(unsigned)((nx + 255) / 256), 256>>>(x, p_xh, nx);
    size_t nw = (size_t)DIM * DIM / 4;
    to_half<<<(unsigned)((nw + 255) / 256), 256>>>(Wv, p_wvh, nw);
    to_half<<<(unsigned)((nw + 255) / 256), 256>>>(Wo, p_woh, nw);
    size_t nk = (size_t)64 * DIM / 4;
    split3<false><<<(unsigned)((nk + 255) / 256), 256>>>(Wk, p_wkq3, nk);
    split3<false><<<(unsigned)((nk + 255) / 256), 256>>>(Wq, p_wkq3 + (size_t)64 * K3, nk);

    // 2. phase scores (bf16x3, split-K over 3 segments): partials [3][B,128]
    {
        dim3 grid((B_ROWS / BM) * (NPH / BN), 3);
        gemm16<__nv_bfloat16,0><<<grid, 256, GEMM_SMEM>>>(
            p_x3, K3, p_wkq3, K3, DIM, p_phase, B_ROWS, NPH, nullptr, nullptr);
    }

    // 3. per-row coef
    coef_kernel<<<B_ROWS / 8, 256>>>(bk, bq);

    // 4. V raw: [B,DIM] = x @ Wv^T   (fp16 single)
    gemm16<__half,0><<<dim3((B_ROWS / BM) * (DIM / BN), 1), 256, GEMM_SMEM>>>(
        p_xh, DIM, p_wvh, DIM, DIM, p_V, B_ROWS, DIM, nullptr, nullptr);

    // 5. bias + coef scale + LayerNorm -> fp16 normed
    ln_kernel<<<B_ROWS, 256>>>(bv, ln_g, ln_b);

    // 6. out = x + normed @ Wo^T + bo   (fp16 single)
    gemm16<__half,1><<<dim3((B_ROWS / BM) * (DIM / BN), 1), 256, GEMM_SMEM>>>(
        p_nh, DIM, p_woh, DIM, DIM, out, B_ROWS, DIM, bo, x);
}